// round 2
// baseline (speedup 1.0000x reference)
#include <cuda_runtime.h>
#include <cstdint>

// GRU: B=256, T=2048, I=10, H=64. PyTorch gate order (r, z, n).
// One CTA per batch row; h in SMEM; 192 threads = one per gate pre-activation row.
// Recurrent dot uses packed fma.rn.f32x2 (FFMA2) for 2x fp32 FMA throughput.
// Input x prefetched in 32-step chunks via cp.async double buffering.

#define BB 256
#define TT 2048
#define II 10
#define HH 64
#define GG 192           // 3*H
#define CHUNK 32         // timesteps per prefetch chunk
#define NCH (TT / CHUNK) // 64 chunks
#define CPOPS ((CHUNK * II * 4) / 16) // 80 x 16B cp.async per chunk

__device__ __forceinline__ uint64_t fma2(uint64_t a, uint64_t b, uint64_t c) {
    uint64_t d;
    asm("fma.rn.f32x2 %0, %1, %2, %3;" : "=l"(d) : "l"(a), "l"(b), "l"(c));
    return d;
}

__device__ __forceinline__ void cp16(uint32_t saddr, const void* gptr) {
    asm volatile("cp.async.ca.shared.global [%0], [%1], 16;" :: "r"(saddr), "l"(gptr));
}

__device__ __forceinline__ float f2lo(uint64_t v) { return __uint_as_float((uint32_t)v); }
__device__ __forceinline__ float f2hi(uint64_t v) { return __uint_as_float((uint32_t)(v >> 32)); }

__global__ __launch_bounds__(GG, 2) void gru_kernel(
    const float* __restrict__ noise,   // (B, T, I)
    const float* __restrict__ w_ih,    // (3H, I)
    const float* __restrict__ w_hh,    // (3H, H)
    const float* __restrict__ b_ih,    // (3H)
    const float* __restrict__ b_hh,    // (3H)
    float* __restrict__ out)           // (B, T, H)
{
    const int b = blockIdx.x;
    const int g = threadIdx.x;   // 0..191: gate row. 0-63 r, 64-127 z, 128-191 n

    __shared__ __align__(16) float hs[HH];
    __shared__ __align__(16) float pre[4][HH];          // pre_r, pre_z, n_hpart, n_gpart
    __shared__ __align__(16) float xs[2][CHUNK * II];   // double-buffered input chunk

    // --- Load this thread's weight row into registers ---
    uint64_t wp[HH / 2];   // 32 packed f32x2 pairs of w_hh row g
    {
        const uint64_t* wrow = reinterpret_cast<const uint64_t*>(w_hh + g * HH);
        #pragma unroll
        for (int k = 0; k < HH / 2; k++) wp[k] = wrow[k];
    }
    float wi[II];
    #pragma unroll
    for (int j = 0; j < II; j++) wi[j] = w_ih[g * II + j];
    const float bi = b_ih[g];
    const float bh = b_hh[g];

    if (g < HH) hs[g] = 0.0f;   // h0 = 0

    const float* xg = noise + (size_t)b * TT * II;
    float* outb = out + (size_t)b * TT * HH;

    // Prefetch chunk 0
    if (g < CPOPS)
        cp16((uint32_t)__cvta_generic_to_shared(&xs[0][g * 4]), xg + g * 4);
    asm volatile("cp.async.commit_group;");

    int buf = 0;
    #pragma unroll 1
    for (int c = 0; c < NCH; ++c) {
        // Prefetch next chunk into the other buffer (empty commit on last chunk
        // keeps wait_group bookkeeping uniform).
        if (c + 1 < NCH && g < CPOPS)
            cp16((uint32_t)__cvta_generic_to_shared(&xs[buf ^ 1][g * 4]),
                 xg + (size_t)(c + 1) * CHUNK * II + g * 4);
        asm volatile("cp.async.commit_group;");
        asm volatile("cp.async.wait_group 1;");   // chunk c landed
        __syncthreads();

        #pragma unroll 1
        for (int s = 0; s < CHUNK; ++s) {
            // ---- recurrent dot: acc_h = h . w_hh_row  (packed f32x2, 2 chains) ----
            const uint64_t* hp = reinterpret_cast<const uint64_t*>(hs);
            uint64_t a0 = 0ull, a1 = 0ull;
            #pragma unroll
            for (int k = 0; k < HH / 2; k += 2) {
                a0 = fma2(wp[k],     hp[k],     a0);
                a1 = fma2(wp[k + 1], hp[k + 1], a1);
            }
            float acch = bh + ((f2lo(a0) + f2hi(a0)) + (f2lo(a1) + f2hi(a1)));

            // ---- input dot: acc_x = x . w_ih_row + b_ih ----
            const float* x = &xs[buf][s * II];
            float accx = bi;
            #pragma unroll
            for (int j = 0; j < II; j++) accx = fmaf(wi[j], x[j], accx);

            const int idx = g & (HH - 1);
            if (g < HH)            pre[0][idx] = accx + acch;       // r pre-act
            else if (g < 2 * HH)   pre[1][idx] = accx + acch;       // z pre-act
            else { pre[2][idx] = acch; pre[3][idx] = accx; }        // n: h-part / g-part
            __syncthreads();

            if (g < HH) {
                float r = 1.0f / (1.0f + __expf(-pre[0][g]));
                float z = 1.0f / (1.0f + __expf(-pre[1][g]));
                float n = tanhf(pre[3][g] + r * pre[2][g]);
                float hnew = n + z * (hs[g] - n);   // (1-z)*n + z*h
                hs[g] = hnew;
                outb[(size_t)(c * CHUNK + s) * HH + g] = hnew;
            }
            __syncthreads();   // new h visible before next step's dot
        }
        buf ^= 1;
    }
}

extern "C" void kernel_launch(void* const* d_in, const int* in_sizes, int n_in,
                              void* d_out, int out_size) {
    const float* noise = (const float*)d_in[0];
    const float* w_ih  = (const float*)d_in[1];
    const float* w_hh  = (const float*)d_in[2];
    const float* b_ih  = (const float*)d_in[3];
    const float* b_hh  = (const float*)d_in[4];
    float* out = (float*)d_out;
    gru_kernel<<<BB, GG>>>(noise, w_ih, w_hh, b_ih, b_hh, out);
}

// round 3
// speedup vs baseline: 1.4058x; 1.4058x over previous
#include <cuda_runtime.h>
#include <cstdint>

// GRU: B=256, T=2048, I=10, H=64. PyTorch gate order (r, z, n).
// 2 batch rows per CTA (384 threads), named barriers per half so the two
// batches overlap freely. h in SMEM (LDS.128), w_hh row in registers,
// packed fma.rn.f32x2 dots, cp.async double-buffered input chunks,
// input-dot software-pipelined into the activation phase.

#define BB 256
#define TT 2048
#define II 10
#define HH 64
#define GG 192            // 3*H
#define BPC 2             // batches per CTA
#define NT (GG * BPC)     // 384 threads
#define CHUNK 64          // timesteps per prefetch chunk
#define NCH (TT / CHUNK)  // 32 chunks
#define CPOPS ((CHUNK * II * 4) / 16) // 160 x 16B cp.async per chunk per half

__device__ __forceinline__ uint64_t fma2(uint64_t a, uint64_t b, uint64_t c) {
    uint64_t d;
    asm("fma.rn.f32x2 %0, %1, %2, %3;" : "=l"(d) : "l"(a), "l"(b), "l"(c));
    return d;
}
__device__ __forceinline__ void cp16(uint32_t saddr, const void* gptr) {
    asm volatile("cp.async.ca.shared.global [%0], [%1], 16;" :: "r"(saddr), "l"(gptr));
}
__device__ __forceinline__ float f2lo(uint64_t v) { return __uint_as_float((uint32_t)v); }
__device__ __forceinline__ float f2hi(uint64_t v) { return __uint_as_float((uint32_t)(v >> 32)); }
__device__ __forceinline__ void barh(int half) {   // per-half named barrier
    asm volatile("bar.sync %0, %1;" :: "r"(half + 1), "r"(GG) : "memory");
}
__device__ __forceinline__ float sigm(float x) { return 1.0f / (1.0f + __expf(-x)); }
__device__ __forceinline__ float tanh_fast(float x) {
    return 1.0f - 2.0f / (1.0f + __expf(2.0f * x));
}

__global__ __launch_bounds__(NT, 1) void gru_kernel(
    const float* __restrict__ noise,   // (B, T, I)
    const float* __restrict__ w_ih,    // (3H, I)
    const float* __restrict__ w_hh,    // (3H, H)
    const float* __restrict__ b_ih,    // (3H)
    const float* __restrict__ b_hh,    // (3H)
    float* __restrict__ out)           // (B, T, H)
{
    const int half = (threadIdx.x >= GG) ? 1 : 0;
    const int g = threadIdx.x - half * GG;     // 0..191 gate row within batch
    const int b = blockIdx.x * BPC + half;

    __shared__ __align__(16) float hs[BPC][HH];
    __shared__ __align__(16) float pre[BPC][4][HH];      // r, z, n_hpart, n_gpart
    __shared__ __align__(16) float xs[BPC][2][CHUNK * II];

    // --- weights into registers ---
    uint64_t wp[HH / 2];    // w_hh row g, packed f32x2
    {
        const uint64_t* wrow = reinterpret_cast<const uint64_t*>(w_hh + g * HH);
        #pragma unroll
        for (int k = 0; k < HH / 2; k++) wp[k] = wrow[k];
    }
    uint64_t wip[II / 2];   // w_ih row g, packed f32x2 (8B-aligned: 40B stride)
    {
        const uint64_t* wrow = reinterpret_cast<const uint64_t*>(w_ih + g * II);
        #pragma unroll
        for (int k = 0; k < II / 2; k++) wip[k] = wrow[k];
    }
    const float bi = b_ih[g];
    const float bh = b_hh[g];

    if (g < HH) hs[half][g] = 0.0f;   // h0

    const float* xg = noise + (size_t)b * TT * II;
    float* outb = out + (size_t)b * TT * HH;

    // prefetch chunk 0 for this half
    if (g < CPOPS)
        cp16((uint32_t)__cvta_generic_to_shared(&xs[half][0][g * 4]), xg + g * 4);
    asm volatile("cp.async.commit_group;");

    int buf = 0;
    #pragma unroll 1
    for (int c = 0; c < NCH; ++c) {
        if (c + 1 < NCH && g < CPOPS)
            cp16((uint32_t)__cvta_generic_to_shared(&xs[half][buf ^ 1][g * 4]),
                 xg + (size_t)(c + 1) * CHUNK * II + g * 4);
        asm volatile("cp.async.commit_group;");
        asm volatile("cp.async.wait_group 1;");
        barh(half);

        // input dot for step 0 of this chunk
        uint64_t ax;
        {
            const uint64_t* xp = reinterpret_cast<const uint64_t*>(&xs[half][buf][0]);
            uint64_t t = 0ull;
            #pragma unroll
            for (int k = 0; k < II / 2; k++) t = fma2(wip[k], xp[k], t);
            ax = t;
        }

        #pragma unroll 1
        for (int s = 0; s < CHUNK; ++s) {
            // ---- recurrent dot (LDS.128 + f32x2, 2 accumulator chains) ----
            const ulonglong2* hp = reinterpret_cast<const ulonglong2*>(hs[half]);
            uint64_t a0 = 0ull, a1 = 0ull;
            #pragma unroll
            for (int k = 0; k < HH / 4; k++) {
                ulonglong2 v = hp[k];
                a0 = fma2(wp[2 * k],     v.x, a0);
                a1 = fma2(wp[2 * k + 1], v.y, a1);
            }
            float acch = bh + ((f2lo(a0) + f2hi(a0)) + (f2lo(a1) + f2hi(a1)));
            float accx = bi + (f2lo(ax) + f2hi(ax));

            const int idx = g & (HH - 1);
            if (g < HH)            pre[half][0][idx] = accx + acch;
            else if (g < 2 * HH)   pre[half][1][idx] = accx + acch;
            else { pre[half][2][idx] = acch; pre[half][3][idx] = accx; }
            barh(half);

            // ---- software-pipelined input dot for next step (h-independent) ----
            if (s + 1 < CHUNK) {
                const uint64_t* xp =
                    reinterpret_cast<const uint64_t*>(&xs[half][buf][(s + 1) * II]);
                uint64_t t = 0ull;
                #pragma unroll
                for (int k = 0; k < II / 2; k++) t = fma2(wip[k], xp[k], t);
                ax = t;
            }

            // ---- activation + h update (64 threads per half) ----
            if (g < HH) {
                float r = sigm(pre[half][0][g]);
                float z = sigm(pre[half][1][g]);
                float n = tanh_fast(pre[half][3][g] + r * pre[half][2][g]);
                float hnew = n + z * (hs[half][g] - n);   // (1-z)*n + z*h
                hs[half][g] = hnew;
                outb[(size_t)(c * CHUNK + s) * HH + g] = hnew;
            }
            barh(half);   // new h visible before next step's dot
        }
        buf ^= 1;
    }
}

extern "C" void kernel_launch(void* const* d_in, const int* in_sizes, int n_in,
                              void* d_out, int out_size) {
    const float* noise = (const float*)d_in[0];
    const float* w_ih  = (const float*)d_in[1];
    const float* w_hh  = (const float*)d_in[2];
    const float* b_ih  = (const float*)d_in[3];
    const float* b_hh  = (const float*)d_in[4];
    float* out = (float*)d_out;
    gru_kernel<<<BB / BPC, NT>>>(noise, w_ih, w_hh, b_ih, b_hh, out);
}